// round 5
// baseline (speedup 1.0000x reference)
#include <cuda_runtime.h>
#include <math.h>

// ---------------------------------------------------------------------------
// Problem constants
// ---------------------------------------------------------------------------
#define B_     8
#define N_     2048
#define M_     32768
#define QD_    512
#define DR_    256
#define D_     512
#define H_     8
#define DH_    64
#define INNER_ 512
#define TOPK_  8
#define SCALE_ 0.125f

#define DIST_BLOCKS 128   // chunks per batch (256 rows each)
#define NCAND (DIST_BLOCKS * TOPK_)   // 1024 candidates per batch

// ---------------------------------------------------------------------------
// Scratch
// ---------------------------------------------------------------------------
__device__ float g_e0[B_ * DR_];
__device__ float g_cand_d2[B_ * NCAND];
__device__ int   g_cand_idx[B_ * NCAND];
__device__ int   g_topk_idx[B_ * TOPK_];
__device__ float g_WqT[QD_ * INNER_];          // WqT[i][p] = Wq[p][i]
__device__ float g_kappa[B_ * QD_ * 64];       // [b][p][c], c=j*8+h (SCALE folded)
__device__ float g_vw[B_ * 64 * INNER_];       // [b][c][o]
__device__ float g_a[B_ * N_ * 64];            // attention weights [b][n][c]

// ---------------------------------------------------------------------------
// Kernel 0: transpose Wq -> g_WqT
// ---------------------------------------------------------------------------
__global__ void transpose512(const float* __restrict__ Wq) {
    __shared__ float tile[32][33];
    int bx = blockIdx.x * 32, by = blockIdx.y * 32;
    int tx = threadIdx.x & 31, ty = threadIdx.x >> 5;
#pragma unroll
    for (int r = ty; r < 32; r += 8)
        tile[r][tx] = Wq[(by + r) * 512 + bx + tx];
    __syncthreads();
#pragma unroll
    for (int r = ty; r < 32; r += 8)
        g_WqT[(bx + r) * 512 + by + tx] = tile[tx][r];
}

// ---------------------------------------------------------------------------
// Kernel 1: e0[b,:] = (x[b,0,:] @ Wq) @ We   — deep unroll for MLP
// ---------------------------------------------------------------------------
__global__ void e0_kernel(const float* __restrict__ x,
                          const float* __restrict__ Wq,
                          const float* __restrict__ We) {
    int b = blockIdx.x;
    int tid = threadIdx.x;  // 512
    __shared__ float xs[QD_];
    __shared__ float q0[QD_];

    xs[tid] = x[(long)b * N_ * QD_ + tid];
    __syncthreads();

    {
        float acc = 0.f;
#pragma unroll 16
        for (int c = 0; c < QD_; c++)
            acc += xs[c] * Wq[c * INNER_ + tid];
        q0[tid] = acc;
    }
    __syncthreads();

    if (tid < DR_) {
        float acc = 0.f;
#pragma unroll 16
        for (int c = 0; c < INNER_; c++)
            acc += q0[c] * We[c * DR_ + tid];
        g_e0[b * DR_ + tid] = acc;
    }
}

// ---------------------------------------------------------------------------
// Kernel 2: distance scan + local top-8. grid (DIST_BLOCKS, B), 256 thr.
// Warp-per-row, 32 rows per warp.
// ---------------------------------------------------------------------------
__global__ void dist_topk_kernel(const float* __restrict__ ctx) {
    int b = blockIdx.y;
    int chunk = blockIdx.x;
    int tid = threadIdx.x;
    int warp = tid >> 5, lane = tid & 31;

    __shared__ float es[DR_];
    __shared__ float s_d2[8][TOPK_];
    __shared__ int   s_ix[8][TOPK_];

    if (tid < DR_) es[tid] = g_e0[b * DR_ + tid];
    __syncthreads();

    const float4* e4 = (const float4*)es;
    float4 ea = e4[lane];
    float4 eb = e4[lane + 32];

    float best[TOPK_];
    int   bidx[TOPK_];
#pragma unroll
    for (int i = 0; i < TOPK_; i++) { best[i] = 3.0e38f; bidx[i] = -1; }

    int row0 = chunk * 256 + warp * 32;
#pragma unroll 2
    for (int r = 0; r < 32; r++) {
        int row = row0 + r;
        const float4* crow = (const float4*)(ctx + ((long)b * M_ + row) * D_);
        float4 ca = crow[lane];
        float4 cb = crow[lane + 32];
        float dx, d2 = 0.f;
        dx = ca.x - ea.x; d2 += dx * dx;
        dx = ca.y - ea.y; d2 += dx * dx;
        dx = ca.z - ea.z; d2 += dx * dx;
        dx = ca.w - ea.w; d2 += dx * dx;
        dx = cb.x - eb.x; d2 += dx * dx;
        dx = cb.y - eb.y; d2 += dx * dx;
        dx = cb.z - eb.z; d2 += dx * dx;
        dx = cb.w - eb.w; d2 += dx * dx;
#pragma unroll
        for (int off = 16; off; off >>= 1)
            d2 += __shfl_down_sync(0xffffffffu, d2, off);
        if (lane == 0 && d2 < best[TOPK_ - 1]) {
            int p = TOPK_ - 1;
            while (p > 0 && best[p - 1] > d2) {
                best[p] = best[p - 1]; bidx[p] = bidx[p - 1]; p--;
            }
            best[p] = d2; bidx[p] = row;
        }
    }

    if (lane == 0) {
#pragma unroll
        for (int i = 0; i < TOPK_; i++) { s_d2[warp][i] = best[i]; s_ix[warp][i] = bidx[i]; }
    }
    __syncthreads();

    if (tid == 0) {
        float fb[TOPK_]; int fi[TOPK_];
#pragma unroll
        for (int i = 0; i < TOPK_; i++) { fb[i] = 3.0e38f; fi[i] = -1; }
        for (int w = 0; w < 8; w++)
            for (int i = 0; i < TOPK_; i++) {
                float d2 = s_d2[w][i];
                if (d2 < fb[TOPK_ - 1]) {
                    int ix = s_ix[w][i];
                    int p = TOPK_ - 1;
                    while (p > 0 && fb[p - 1] > d2) {
                        fb[p] = fb[p - 1]; fi[p] = fi[p - 1]; p--;
                    }
                    fb[p] = d2; fi[p] = ix;
                }
            }
        int off = (b * DIST_BLOCKS + chunk) * TOPK_;
        for (int i = 0; i < TOPK_; i++) { g_cand_d2[off + i] = fb[i]; g_cand_idx[off + i] = fi[i]; }
    }
}

// ---------------------------------------------------------------------------
// Kernel 3: parallel merge -> global per-batch top-8 (u64 keys, argmin x8)
// grid B, 256 threads
// ---------------------------------------------------------------------------
__device__ __forceinline__ unsigned long long u64min(unsigned long long a,
                                                     unsigned long long b) {
    return a < b ? a : b;
}
__global__ void __launch_bounds__(256)
topk_merge_kernel() {
    int b = blockIdx.x;
    int tid = threadIdx.x;
    __shared__ unsigned long long keys[NCAND];
    __shared__ unsigned long long red[256];

    int base = b * NCAND;
    for (int i = tid; i < NCAND; i += 256) {
        float d2 = g_cand_d2[base + i];
        int ix = g_cand_idx[base + i];
        unsigned long long k =
            ((unsigned long long)__float_as_uint(d2) << 32) | (unsigned int)ix;
        if (ix < 0) k = ~0ULL;
        keys[i] = k;
    }
    __syncthreads();

    for (int sel = 0; sel < TOPK_; sel++) {
        unsigned long long m = ~0ULL;
        for (int i = tid; i < NCAND; i += 256) m = u64min(m, keys[i]);
        red[tid] = m;
        __syncthreads();
#pragma unroll
        for (int s = 128; s > 0; s >>= 1) {
            if (tid < s) red[tid] = u64min(red[tid], red[tid + s]);
            __syncthreads();
        }
        unsigned long long w = red[0];
        if (tid == 0)
            g_topk_idx[b * TOPK_ + sel] = (int)(unsigned int)(w & 0xffffffffu);
        for (int i = tid; i < NCAND; i += 256)
            if (keys[i] == w) keys[i] = ~0ULL;
        __syncthreads();
    }
}

// ---------------------------------------------------------------------------
// Kernel 4: fused kv + kappa + vw.  grid (64 bj, 4 slice), 512 thr.
// Each block: gather row, k=labels@Wk, v=reps@Wv (full, cheap);
// then kappa/vw for a 128-wide p/o slice, 2 heads per thread.
// ---------------------------------------------------------------------------
__global__ void __launch_bounds__(512)
kvkv_kernel(const float* __restrict__ ctx,
            const float* __restrict__ Wk,
            const float* __restrict__ Wv,
            const float* __restrict__ Wout) {
    int bj = blockIdx.x;
    int slice = blockIdx.y;
    int b = bj >> 3, j = bj & 7;
    int tid = threadIdx.x;  // 512

    __shared__ float labels[DR_];
    __shared__ float reps[DR_];
    __shared__ float kvec[INNER_];
    __shared__ float vvec[INNER_];

    int row = g_topk_idx[bj];
    const float* crow = ctx + ((long)b * M_ + row) * D_;
    if (tid < 256) reps[tid] = crow[tid];
    else           labels[tid - 256] = crow[tid];
    __syncthreads();

    {
        float ak = 0.f, av = 0.f;
#pragma unroll 8
        for (int r = 0; r < DR_; r++) {
            float l = labels[r], rr = reps[r];
            ak += l * Wk[r * INNER_ + tid];
            av += rr * Wv[r * INNER_ + tid];
        }
        kvec[tid] = ak;
        vvec[tid] = av;
    }
    __syncthreads();

    int hp = tid >> 7;           // 0..3 -> heads hp and hp+4
    int pl = tid & 127;
    int p = slice * 128 + pl;    // p (for kappa) == o (for vw)

    // kappa
    {
        float aK0 = 0.f, aK1 = 0.f;
#pragma unroll 8
        for (int d = 0; d < 64; d++) {
            int i0 = hp * 64 + d;
            int i1 = (hp + 4) * 64 + d;
            aK0 += g_WqT[i0 * 512 + p] * kvec[i0];
            aK1 += g_WqT[i1 * 512 + p] * kvec[i1];
        }
        long kb = ((long)b * 512 + p) * 64 + j * 8;
        g_kappa[kb + hp]     = aK0 * SCALE_;
        g_kappa[kb + hp + 4] = aK1 * SCALE_;
    }

    // vw
    {
        float aV0 = 0.f, aV1 = 0.f;
#pragma unroll 8
        for (int d = 0; d < 64; d++) {
            int i0 = hp * 64 + d;
            int i1 = (hp + 4) * 64 + d;
            aV0 += Wout[i0 * 512 + p] * vvec[i0];
            aV1 += Wout[i1 * 512 + p] * vvec[i1];
        }
        g_vw[((long)b * 64 + j * 8 + hp) * 512 + p]     = aV0;
        g_vw[((long)b * 64 + j * 8 + hp + 4) * 512 + p] = aV1;
    }
}

// ---------------------------------------------------------------------------
// Kernel 5: sim + softmax. grid (16 nchunk, B), 256 thr. M-tile=128 tokens.
// sim[n,c] = x[b,n,:]·kappa[b,:,c]; softmax over j per (token, head).
// ---------------------------------------------------------------------------
__global__ void __launch_bounds__(256)
simA_kernel(const float* __restrict__ x) {
    int nc = blockIdx.x, b = blockIdx.y;
    int n0 = nc * 128;
    int tid = threadIdx.x;
    int ty = tid >> 4, tx = tid & 15;   // ty: 8-row group, tx: 4-col group

    __shared__ float xs[128 * 68];
    __shared__ float ks[64 * 68];

    float acc[8][4];
#pragma unroll
    for (int t = 0; t < 8; t++)
#pragma unroll
        for (int c = 0; c < 4; c++) acc[t][c] = 0.f;

    const float* xb = x + ((long)b * N_ + n0) * QD_;
    const float* kb = g_kappa + (long)b * QD_ * 64;

    for (int pc = 0; pc < 8; pc++) {
        int p0 = pc * 64;
#pragma unroll
        for (int l = 0; l < 8; l++) {
            int f = tid + l * 256;
            int row = f >> 4, c4 = (f & 15) * 4;
            *(float4*)&xs[row * 68 + c4] =
                *(const float4*)(xb + (long)row * QD_ + p0 + c4);
        }
#pragma unroll
        for (int l = 0; l < 4; l++) {
            int f = tid + l * 256;
            int row = f >> 4, c4 = (f & 15) * 4;
            *(float4*)&ks[row * 68 + c4] =
                *(const float4*)(kb + (long)(p0 + row) * 64 + c4);
        }
        __syncthreads();
#pragma unroll
        for (int kk = 0; kk < 64; kk += 4) {
            float4 av[8], bv[4];
#pragma unroll
            for (int t = 0; t < 8; t++)
                av[t] = *(const float4*)&xs[(ty * 8 + t) * 68 + kk];
#pragma unroll
            for (int cc = 0; cc < 4; cc++)
                bv[cc] = *(const float4*)&ks[(kk + cc) * 68 + tx * 4];
#pragma unroll
            for (int t = 0; t < 8; t++) {
                acc[t][0] += av[t].x * bv[0].x; acc[t][1] += av[t].x * bv[0].y;
                acc[t][2] += av[t].x * bv[0].z; acc[t][3] += av[t].x * bv[0].w;
                acc[t][0] += av[t].y * bv[1].x; acc[t][1] += av[t].y * bv[1].y;
                acc[t][2] += av[t].y * bv[1].z; acc[t][3] += av[t].y * bv[1].w;
                acc[t][0] += av[t].z * bv[2].x; acc[t][1] += av[t].z * bv[2].y;
                acc[t][2] += av[t].z * bv[2].z; acc[t][3] += av[t].z * bv[2].w;
                acc[t][0] += av[t].w * bv[3].x; acc[t][1] += av[t].w * bv[3].y;
                acc[t][2] += av[t].w * bv[3].z; acc[t][3] += av[t].w * bv[3].w;
            }
        }
        __syncthreads();
    }

    // dump sim into xs
#pragma unroll
    for (int t = 0; t < 8; t++) {
        float4 v = make_float4(acc[t][0], acc[t][1], acc[t][2], acc[t][3]);
        *(float4*)&xs[(ty * 8 + t) * 68 + tx * 4] = v;
    }
    __syncthreads();

    // softmax: 128 tokens x 8 heads = 1024 tasks, 4 per thread
#pragma unroll
    for (int s = 0; s < 4; s++) {
        int task = s * 256 + tid;
        int t = task >> 3, h = task & 7;
        float v[8];
#pragma unroll
        for (int jj = 0; jj < 8; jj++) v[jj] = xs[t * 68 + jj * 8 + h];
        float m = v[0];
#pragma unroll
        for (int jj = 1; jj < 8; jj++) m = fmaxf(m, v[jj]);
        float e[8], sum = 0.f;
#pragma unroll
        for (int jj = 0; jj < 8; jj++) { e[jj] = __expf(v[jj] - m); sum += e[jj]; }
        float inv = 1.f / sum;
        float* arow = g_a + ((long)b * N_ + n0 + t) * 64;
#pragma unroll
        for (int jj = 0; jj < 8; jj++) arow[jj * 8 + h] = e[jj] * inv;
    }
}

// ---------------------------------------------------------------------------
// Kernel 6: out[n,o] = sum_c a[n,c]*vw[c,o] + bout[o]
// grid (8 oc, 32 nc, B), 256 thr
// ---------------------------------------------------------------------------
__global__ void __launch_bounds__(256)
outB_kernel(float* __restrict__ out, const float* __restrict__ bout) {
    int oc = blockIdx.x, nc = blockIdx.y, b = blockIdx.z;
    int o0 = oc * 64, n0 = nc * 64;
    int tid = threadIdx.x;
    int ty = tid >> 4, tx = tid & 15;

    __shared__ float as_[64 * 68];
    __shared__ float vws[64 * 68];

#pragma unroll
    for (int l = 0; l < 4; l++) {
        int f = tid + l * 256;
        int row = f >> 4, c4 = (f & 15) * 4;
        *(float4*)&as_[row * 68 + c4] =
            *(const float4*)(g_a + ((long)b * N_ + n0 + row) * 64 + c4);
        *(float4*)&vws[row * 68 + c4] =
            *(const float4*)(g_vw + ((long)b * 64 + row) * 512 + o0 + c4);
    }
    __syncthreads();

    float acc[4][4];
#pragma unroll
    for (int t = 0; t < 4; t++)
#pragma unroll
        for (int o = 0; o < 4; o++) acc[t][o] = 0.f;

#pragma unroll
    for (int c = 0; c < 64; c += 4) {
        float4 av[4], bv[4];
#pragma unroll
        for (int t = 0; t < 4; t++) av[t] = *(const float4*)&as_[(ty * 4 + t) * 68 + c];
#pragma unroll
        for (int cc = 0; cc < 4; cc++) bv[cc] = *(const float4*)&vws[(c + cc) * 68 + tx * 4];
#pragma unroll
        for (int t = 0; t < 4; t++) {
            acc[t][0] += av[t].x * bv[0].x; acc[t][1] += av[t].x * bv[0].y;
            acc[t][2] += av[t].x * bv[0].z; acc[t][3] += av[t].x * bv[0].w;
            acc[t][0] += av[t].y * bv[1].x; acc[t][1] += av[t].y * bv[1].y;
            acc[t][2] += av[t].y * bv[1].z; acc[t][3] += av[t].y * bv[1].w;
            acc[t][0] += av[t].z * bv[2].x; acc[t][1] += av[t].z * bv[2].y;
            acc[t][2] += av[t].z * bv[2].z; acc[t][3] += av[t].z * bv[2].w;
            acc[t][0] += av[t].w * bv[3].x; acc[t][1] += av[t].w * bv[3].y;
            acc[t][2] += av[t].w * bv[3].z; acc[t][3] += av[t].w * bv[3].w;
        }
    }

    float4 bias = *(const float4*)(bout + o0 + tx * 4);
#pragma unroll
    for (int t = 0; t < 4; t++) {
        float4 r = make_float4(acc[t][0] + bias.x, acc[t][1] + bias.y,
                               acc[t][2] + bias.z, acc[t][3] + bias.w);
        *(float4*)(out + ((long)b * N_ + n0 + ty * 4 + t) * 512 + o0 + tx * 4) = r;
    }
}

// ---------------------------------------------------------------------------
// Launch
// ---------------------------------------------------------------------------
extern "C" void kernel_launch(void* const* d_in, const int* in_sizes, int n_in,
                              void* d_out, int out_size) {
    const float* x    = (const float*)d_in[0];
    const float* ctx  = (const float*)d_in[1];
    const float* Wq   = (const float*)d_in[2];
    const float* Wk   = (const float*)d_in[3];
    const float* Wv   = (const float*)d_in[4];
    const float* We   = (const float*)d_in[5];
    const float* Wout = (const float*)d_in[6];
    const float* bout = (const float*)d_in[7];
    float* out = (float*)d_out;

    transpose512<<<dim3(16, 16), 256>>>(Wq);
    e0_kernel<<<B_, 512>>>(x, Wq, We);
    dist_topk_kernel<<<dim3(DIST_BLOCKS, B_), 256>>>(ctx);
    topk_merge_kernel<<<B_, 256>>>();
    kvkv_kernel<<<dim3(64, 4), 512>>>(ctx, Wk, Wv, Wout);
    simA_kernel<<<dim3(16, B_), 256>>>(x);
    outB_kernel<<<dim3(8, 32, B_), 256>>>(out, bout);
}

// round 6
// speedup vs baseline: 1.0072x; 1.0072x over previous
#include <cuda_runtime.h>
#include <math.h>

// ---------------------------------------------------------------------------
// Problem constants
// ---------------------------------------------------------------------------
#define B_     8
#define N_     2048
#define M_     32768
#define QD_    512
#define DR_    256
#define D_     512
#define H_     8
#define DH_    64
#define INNER_ 512
#define TOPK_  8
#define SCALE_ 0.125f

#define DIST_BLOCKS 128   // chunks per batch (256 rows each)
#define NCAND (DIST_BLOCKS * TOPK_)   // 1024 candidates per batch

// ---------------------------------------------------------------------------
// Scratch
// ---------------------------------------------------------------------------
__device__ float g_e0[B_ * DR_];
__device__ float g_cand_d2[B_ * NCAND];
__device__ int   g_cand_idx[B_ * NCAND];
__device__ int   g_topk_idx[B_ * TOPK_];
__device__ float g_WqT[QD_ * INNER_];          // WqT[i][p] = Wq[p][i]
__device__ float g_kappa[B_ * QD_ * 64];       // [b][p][c], c=j*8+h (SCALE folded)
__device__ float g_vw[B_ * 64 * INNER_];       // [b][c][o]
__device__ float g_a[B_ * N_ * 64];            // attention weights [b][n][c]

// ---------------------------------------------------------------------------
// Kernel 0: transpose Wq -> g_WqT
// ---------------------------------------------------------------------------
__global__ void transpose512(const float* __restrict__ Wq) {
    __shared__ float tile[32][33];
    int bx = blockIdx.x * 32, by = blockIdx.y * 32;
    int tx = threadIdx.x & 31, ty = threadIdx.x >> 5;
#pragma unroll
    for (int r = ty; r < 32; r += 8)
        tile[r][tx] = Wq[(by + r) * 512 + bx + tx];
    __syncthreads();
#pragma unroll
    for (int r = ty; r < 32; r += 8)
        g_WqT[(bx + r) * 512 + by + tx] = tile[tx][r];
}

// ---------------------------------------------------------------------------
// Kernel 1: e0[b,:] = (x[b,0,:] @ Wq) @ We   — deep unroll for MLP
// ---------------------------------------------------------------------------
__global__ void e0_kernel(const float* __restrict__ x,
                          const float* __restrict__ Wq,
                          const float* __restrict__ We) {
    int b = blockIdx.x;
    int tid = threadIdx.x;  // 512
    __shared__ float xs[QD_];
    __shared__ float q0[QD_];

    xs[tid] = x[(long)b * N_ * QD_ + tid];
    __syncthreads();

    {
        float acc = 0.f;
#pragma unroll 16
        for (int c = 0; c < QD_; c++)
            acc += xs[c] * Wq[c * INNER_ + tid];
        q0[tid] = acc;
    }
    __syncthreads();

    if (tid < DR_) {
        float acc = 0.f;
#pragma unroll 16
        for (int c = 0; c < INNER_; c++)
            acc += q0[c] * We[c * DR_ + tid];
        g_e0[b * DR_ + tid] = acc;
    }
}

// ---------------------------------------------------------------------------
// Kernel 2: distance scan + local top-8. grid (DIST_BLOCKS, B), 256 thr.
// Warp-per-row, 32 rows per warp.
// ---------------------------------------------------------------------------
__global__ void dist_topk_kernel(const float* __restrict__ ctx) {
    int b = blockIdx.y;
    int chunk = blockIdx.x;
    int tid = threadIdx.x;
    int warp = tid >> 5, lane = tid & 31;

    __shared__ float es[DR_];
    __shared__ float s_d2[8][TOPK_];
    __shared__ int   s_ix[8][TOPK_];

    if (tid < DR_) es[tid] = g_e0[b * DR_ + tid];
    __syncthreads();

    const float4* e4 = (const float4*)es;
    float4 ea = e4[lane];
    float4 eb = e4[lane + 32];

    float best[TOPK_];
    int   bidx[TOPK_];
#pragma unroll
    for (int i = 0; i < TOPK_; i++) { best[i] = 3.0e38f; bidx[i] = -1; }

    int row0 = chunk * 256 + warp * 32;
#pragma unroll 2
    for (int r = 0; r < 32; r++) {
        int row = row0 + r;
        const float4* crow = (const float4*)(ctx + ((long)b * M_ + row) * D_);
        float4 ca = crow[lane];
        float4 cb = crow[lane + 32];
        float dx, d2 = 0.f;
        dx = ca.x - ea.x; d2 += dx * dx;
        dx = ca.y - ea.y; d2 += dx * dx;
        dx = ca.z - ea.z; d2 += dx * dx;
        dx = ca.w - ea.w; d2 += dx * dx;
        dx = cb.x - eb.x; d2 += dx * dx;
        dx = cb.y - eb.y; d2 += dx * dx;
        dx = cb.z - eb.z; d2 += dx * dx;
        dx = cb.w - eb.w; d2 += dx * dx;
#pragma unroll
        for (int off = 16; off; off >>= 1)
            d2 += __shfl_down_sync(0xffffffffu, d2, off);
        if (lane == 0 && d2 < best[TOPK_ - 1]) {
            int p = TOPK_ - 1;
            while (p > 0 && best[p - 1] > d2) {
                best[p] = best[p - 1]; bidx[p] = bidx[p - 1]; p--;
            }
            best[p] = d2; bidx[p] = row;
        }
    }

    if (lane == 0) {
#pragma unroll
        for (int i = 0; i < TOPK_; i++) { s_d2[warp][i] = best[i]; s_ix[warp][i] = bidx[i]; }
    }
    __syncthreads();

    if (tid == 0) {
        float fb[TOPK_]; int fi[TOPK_];
#pragma unroll
        for (int i = 0; i < TOPK_; i++) { fb[i] = 3.0e38f; fi[i] = -1; }
        for (int w = 0; w < 8; w++)
            for (int i = 0; i < TOPK_; i++) {
                float d2 = s_d2[w][i];
                if (d2 < fb[TOPK_ - 1]) {
                    int ix = s_ix[w][i];
                    int p = TOPK_ - 1;
                    while (p > 0 && fb[p - 1] > d2) {
                        fb[p] = fb[p - 1]; fi[p] = fi[p - 1]; p--;
                    }
                    fb[p] = d2; fi[p] = ix;
                }
            }
        int off = (b * DIST_BLOCKS + chunk) * TOPK_;
        for (int i = 0; i < TOPK_; i++) { g_cand_d2[off + i] = fb[i]; g_cand_idx[off + i] = fi[i]; }
    }
}

// ---------------------------------------------------------------------------
// Kernel 3: parallel merge -> global per-batch top-8 (u64 keys, argmin x8)
// grid B, 256 threads
// ---------------------------------------------------------------------------
__device__ __forceinline__ unsigned long long u64min(unsigned long long a,
                                                     unsigned long long b) {
    return a < b ? a : b;
}
__global__ void __launch_bounds__(256)
topk_merge_kernel() {
    int b = blockIdx.x;
    int tid = threadIdx.x;
    __shared__ unsigned long long keys[NCAND];
    __shared__ unsigned long long red[256];

    int base = b * NCAND;
    for (int i = tid; i < NCAND; i += 256) {
        float d2 = g_cand_d2[base + i];
        int ix = g_cand_idx[base + i];
        unsigned long long k =
            ((unsigned long long)__float_as_uint(d2) << 32) | (unsigned int)ix;
        if (ix < 0) k = ~0ULL;
        keys[i] = k;
    }
    __syncthreads();

    for (int sel = 0; sel < TOPK_; sel++) {
        unsigned long long m = ~0ULL;
        for (int i = tid; i < NCAND; i += 256) m = u64min(m, keys[i]);
        red[tid] = m;
        __syncthreads();
#pragma unroll
        for (int s = 128; s > 0; s >>= 1) {
            if (tid < s) red[tid] = u64min(red[tid], red[tid + s]);
            __syncthreads();
        }
        unsigned long long w = red[0];
        if (tid == 0)
            g_topk_idx[b * TOPK_ + sel] = (int)(unsigned int)(w & 0xffffffffu);
        for (int i = tid; i < NCAND; i += 256)
            if (keys[i] == w) keys[i] = ~0ULL;
        __syncthreads();
    }
}

// ---------------------------------------------------------------------------
// Kernel 4: fused kv + kappa + vw.  grid (64 bj, 4 slice), 512 thr.
// Each block: gather row, k=labels@Wk, v=reps@Wv (full, cheap);
// then kappa/vw for a 128-wide p/o slice, 2 heads per thread.
// ---------------------------------------------------------------------------
__global__ void __launch_bounds__(512)
kvkv_kernel(const float* __restrict__ ctx,
            const float* __restrict__ Wk,
            const float* __restrict__ Wv,
            const float* __restrict__ Wout) {
    int bj = blockIdx.x;
    int slice = blockIdx.y;
    int b = bj >> 3, j = bj & 7;
    int tid = threadIdx.x;  // 512

    __shared__ float labels[DR_];
    __shared__ float reps[DR_];
    __shared__ float kvec[INNER_];
    __shared__ float vvec[INNER_];

    int row = g_topk_idx[bj];
    const float* crow = ctx + ((long)b * M_ + row) * D_;
    if (tid < 256) reps[tid] = crow[tid];
    else           labels[tid - 256] = crow[tid];
    __syncthreads();

    {
        float ak = 0.f, av = 0.f;
#pragma unroll 8
        for (int r = 0; r < DR_; r++) {
            float l = labels[r], rr = reps[r];
            ak += l * Wk[r * INNER_ + tid];
            av += rr * Wv[r * INNER_ + tid];
        }
        kvec[tid] = ak;
        vvec[tid] = av;
    }
    __syncthreads();

    int hp = tid >> 7;           // 0..3 -> heads hp and hp+4
    int pl = tid & 127;
    int p = slice * 128 + pl;    // p (for kappa) == o (for vw)

    // kappa
    {
        float aK0 = 0.f, aK1 = 0.f;
#pragma unroll 8
        for (int d = 0; d < 64; d++) {
            int i0 = hp * 64 + d;
            int i1 = (hp + 4) * 64 + d;
            aK0 += g_WqT[i0 * 512 + p] * kvec[i0];
            aK1 += g_WqT[i1 * 512 + p] * kvec[i1];
        }
        long kb = ((long)b * 512 + p) * 64 + j * 8;
        g_kappa[kb + hp]     = aK0 * SCALE_;
        g_kappa[kb + hp + 4] = aK1 * SCALE_;
    }

    // vw
    {
        float aV0 = 0.f, aV1 = 0.f;
#pragma unroll 8
        for (int d = 0; d < 64; d++) {
            int i0 = hp * 64 + d;
            int i1 = (hp + 4) * 64 + d;
            aV0 += Wout[i0 * 512 + p] * vvec[i0];
            aV1 += Wout[i1 * 512 + p] * vvec[i1];
        }
        g_vw[((long)b * 64 + j * 8 + hp) * 512 + p]     = aV0;
        g_vw[((long)b * 64 + j * 8 + hp + 4) * 512 + p] = aV1;
    }
}

// ---------------------------------------------------------------------------
// Kernel 5: sim + softmax. grid (16 nchunk, B), 256 thr. M-tile=128 tokens.
// sim[n,c] = x[b,n,:]·kappa[b,:,c]; softmax over j per (token, head).
// ---------------------------------------------------------------------------
__global__ void __launch_bounds__(256)
simA_kernel(const float* __restrict__ x) {
    int nc = blockIdx.x, b = blockIdx.y;
    int n0 = nc * 128;
    int tid = threadIdx.x;
    int ty = tid >> 4, tx = tid & 15;   // ty: 8-row group, tx: 4-col group

    __shared__ float xs[128 * 68];
    __shared__ float ks[64 * 68];

    float acc[8][4];
#pragma unroll
    for (int t = 0; t < 8; t++)
#pragma unroll
        for (int c = 0; c < 4; c++) acc[t][c] = 0.f;

    const float* xb = x + ((long)b * N_ + n0) * QD_;
    const float* kb = g_kappa + (long)b * QD_ * 64;

    for (int pc = 0; pc < 8; pc++) {
        int p0 = pc * 64;
#pragma unroll
        for (int l = 0; l < 8; l++) {
            int f = tid + l * 256;
            int row = f >> 4, c4 = (f & 15) * 4;
            *(float4*)&xs[row * 68 + c4] =
                *(const float4*)(xb + (long)row * QD_ + p0 + c4);
        }
#pragma unroll
        for (int l = 0; l < 4; l++) {
            int f = tid + l * 256;
            int row = f >> 4, c4 = (f & 15) * 4;
            *(float4*)&ks[row * 68 + c4] =
                *(const float4*)(kb + (long)(p0 + row) * 64 + c4);
        }
        __syncthreads();
#pragma unroll
        for (int kk = 0; kk < 64; kk += 4) {
            float4 av[8], bv[4];
#pragma unroll
            for (int t = 0; t < 8; t++)
                av[t] = *(const float4*)&xs[(ty * 8 + t) * 68 + kk];
#pragma unroll
            for (int cc = 0; cc < 4; cc++)
                bv[cc] = *(const float4*)&ks[(kk + cc) * 68 + tx * 4];
#pragma unroll
            for (int t = 0; t < 8; t++) {
                acc[t][0] += av[t].x * bv[0].x; acc[t][1] += av[t].x * bv[0].y;
                acc[t][2] += av[t].x * bv[0].z; acc[t][3] += av[t].x * bv[0].w;
                acc[t][0] += av[t].y * bv[1].x; acc[t][1] += av[t].y * bv[1].y;
                acc[t][2] += av[t].y * bv[1].z; acc[t][3] += av[t].y * bv[1].w;
                acc[t][0] += av[t].z * bv[2].x; acc[t][1] += av[t].z * bv[2].y;
                acc[t][2] += av[t].z * bv[2].z; acc[t][3] += av[t].z * bv[2].w;
                acc[t][0] += av[t].w * bv[3].x; acc[t][1] += av[t].w * bv[3].y;
                acc[t][2] += av[t].w * bv[3].z; acc[t][3] += av[t].w * bv[3].w;
            }
        }
        __syncthreads();
    }

    // dump sim into xs
#pragma unroll
    for (int t = 0; t < 8; t++) {
        float4 v = make_float4(acc[t][0], acc[t][1], acc[t][2], acc[t][3]);
        *(float4*)&xs[(ty * 8 + t) * 68 + tx * 4] = v;
    }
    __syncthreads();

    // softmax: 128 tokens x 8 heads = 1024 tasks, 4 per thread
#pragma unroll
    for (int s = 0; s < 4; s++) {
        int task = s * 256 + tid;
        int t = task >> 3, h = task & 7;
        float v[8];
#pragma unroll
        for (int jj = 0; jj < 8; jj++) v[jj] = xs[t * 68 + jj * 8 + h];
        float m = v[0];
#pragma unroll
        for (int jj = 1; jj < 8; jj++) m = fmaxf(m, v[jj]);
        float e[8], sum = 0.f;
#pragma unroll
        for (int jj = 0; jj < 8; jj++) { e[jj] = __expf(v[jj] - m); sum += e[jj]; }
        float inv = 1.f / sum;
        float* arow = g_a + ((long)b * N_ + n0 + t) * 64;
#pragma unroll
        for (int jj = 0; jj < 8; jj++) arow[jj * 8 + h] = e[jj] * inv;
    }
}

// ---------------------------------------------------------------------------
// Kernel 6: out[n,o] = sum_c a[n,c]*vw[c,o] + bout[o]
// grid (8 oc, 32 nc, B), 256 thr
// ---------------------------------------------------------------------------
__global__ void __launch_bounds__(256)
outB_kernel(float* __restrict__ out, const float* __restrict__ bout) {
    int oc = blockIdx.x, nc = blockIdx.y, b = blockIdx.z;
    int o0 = oc * 64, n0 = nc * 64;
    int tid = threadIdx.x;
    int ty = tid >> 4, tx = tid & 15;

    __shared__ float as_[64 * 68];
    __shared__ float vws[64 * 68];

#pragma unroll
    for (int l = 0; l < 4; l++) {
        int f = tid + l * 256;
        int row = f >> 4, c4 = (f & 15) * 4;
        *(float4*)&as_[row * 68 + c4] =
            *(const float4*)(g_a + ((long)b * N_ + n0 + row) * 64 + c4);
        *(float4*)&vws[row * 68 + c4] =
            *(const float4*)(g_vw + ((long)b * 64 + row) * 512 + o0 + c4);
    }
    __syncthreads();

    float acc[4][4];
#pragma unroll
    for (int t = 0; t < 4; t++)
#pragma unroll
        for (int o = 0; o < 4; o++) acc[t][o] = 0.f;

#pragma unroll
    for (int c = 0; c < 64; c += 4) {
        float4 av[4], bv[4];
#pragma unroll
        for (int t = 0; t < 4; t++) av[t] = *(const float4*)&as_[(ty * 4 + t) * 68 + c];
#pragma unroll
        for (int cc = 0; cc < 4; cc++) bv[cc] = *(const float4*)&vws[(c + cc) * 68 + tx * 4];
#pragma unroll
        for (int t = 0; t < 4; t++) {
            acc[t][0] += av[t].x * bv[0].x; acc[t][1] += av[t].x * bv[0].y;
            acc[t][2] += av[t].x * bv[0].z; acc[t][3] += av[t].x * bv[0].w;
            acc[t][0] += av[t].y * bv[1].x; acc[t][1] += av[t].y * bv[1].y;
            acc[t][2] += av[t].y * bv[1].z; acc[t][3] += av[t].y * bv[1].w;
            acc[t][0] += av[t].z * bv[2].x; acc[t][1] += av[t].z * bv[2].y;
            acc[t][2] += av[t].z * bv[2].z; acc[t][3] += av[t].z * bv[2].w;
            acc[t][0] += av[t].w * bv[3].x; acc[t][1] += av[t].w * bv[3].y;
            acc[t][2] += av[t].w * bv[3].z; acc[t][3] += av[t].w * bv[3].w;
        }
    }

    float4 bias = *(const float4*)(bout + o0 + tx * 4);
#pragma unroll
    for (int t = 0; t < 4; t++) {
        float4 r = make_float4(acc[t][0] + bias.x, acc[t][1] + bias.y,
                               acc[t][2] + bias.z, acc[t][3] + bias.w);
        *(float4*)(out + ((long)b * N_ + n0 + ty * 4 + t) * 512 + o0 + tx * 4) = r;
    }
}

// ---------------------------------------------------------------------------
// Launch
// ---------------------------------------------------------------------------
extern "C" void kernel_launch(void* const* d_in, const int* in_sizes, int n_in,
                              void* d_out, int out_size) {
    const float* x    = (const float*)d_in[0];
    const float* ctx  = (const float*)d_in[1];
    const float* Wq   = (const float*)d_in[2];
    const float* Wk   = (const float*)d_in[3];
    const float* Wv   = (const float*)d_in[4];
    const float* We   = (const float*)d_in[5];
    const float* Wout = (const float*)d_in[6];
    const float* bout = (const float*)d_in[7];
    float* out = (float*)d_out;

    transpose512<<<dim3(16, 16), 256>>>(Wq);
    e0_kernel<<<B_, 512>>>(x, Wq, We);
    dist_topk_kernel<<<dim3(DIST_BLOCKS, B_), 256>>>(ctx);
    topk_merge_kernel<<<B_, 256>>>();
    kvkv_kernel<<<dim3(64, 4), 512>>>(ctx, Wk, Wv, Wout);
    simA_kernel<<<dim3(16, B_), 256>>>(x);
    outB_kernel<<<dim3(8, 32, B_), 256>>>(out, bout);
}

// round 7
// speedup vs baseline: 1.0122x; 1.0049x over previous
#include <cuda_runtime.h>
#include <math.h>

// ---------------------------------------------------------------------------
// Problem constants
// ---------------------------------------------------------------------------
#define B_     8
#define N_     2048
#define M_     32768
#define QD_    512
#define DR_    256
#define D_     512
#define H_     8
#define DH_    64
#define INNER_ 512
#define TOPK_  8
#define SCALE_ 0.125f

#define DIST_BLOCKS 128   // chunks per batch (256 rows each)
#define NCAND (DIST_BLOCKS * TOPK_)   // 1024 candidates per batch

// ---------------------------------------------------------------------------
// Scratch
// ---------------------------------------------------------------------------
__device__ float g_e0[B_ * DR_];
__device__ float g_cand_d2[B_ * NCAND];
__device__ int   g_cand_idx[B_ * NCAND];
__device__ int   g_topk_idx[B_ * TOPK_];
__device__ float g_WqT[QD_ * INNER_];          // WqT[i][p] = Wq[p][i]
__device__ float g_kappa[B_ * QD_ * 64];       // [b][p][c], c=j*8+h (SCALE folded)
__device__ float g_vw[B_ * 64 * INNER_];       // [b][c][o]
__device__ float g_a[B_ * N_ * 64];            // attention weights [b][n][c]

// ---------------------------------------------------------------------------
// Kernel 0: transpose Wq -> g_WqT
// ---------------------------------------------------------------------------
__global__ void transpose512(const float* __restrict__ Wq) {
    __shared__ float tile[32][33];
    int bx = blockIdx.x * 32, by = blockIdx.y * 32;
    int tx = threadIdx.x & 31, ty = threadIdx.x >> 5;
#pragma unroll
    for (int r = ty; r < 32; r += 8)
        tile[r][tx] = Wq[(by + r) * 512 + bx + tx];
    __syncthreads();
#pragma unroll
    for (int r = ty; r < 32; r += 8)
        g_WqT[(bx + r) * 512 + by + tx] = tile[tx][r];
}

// ---------------------------------------------------------------------------
// Kernel 1: e0[b,:] = (x[b,0,:] @ Wq) @ We   — deep unroll for MLP
// ---------------------------------------------------------------------------
__global__ void e0_kernel(const float* __restrict__ x,
                          const float* __restrict__ Wq,
                          const float* __restrict__ We) {
    int b = blockIdx.x;
    int tid = threadIdx.x;  // 512
    __shared__ float xs[QD_];
    __shared__ float q0[QD_];

    xs[tid] = x[(long)b * N_ * QD_ + tid];
    __syncthreads();

    {
        float acc = 0.f;
#pragma unroll 16
        for (int c = 0; c < QD_; c++)
            acc += xs[c] * Wq[c * INNER_ + tid];
        q0[tid] = acc;
    }
    __syncthreads();

    if (tid < DR_) {
        float acc = 0.f;
#pragma unroll 16
        for (int c = 0; c < INNER_; c++)
            acc += q0[c] * We[c * DR_ + tid];
        g_e0[b * DR_ + tid] = acc;
    }
}

// ---------------------------------------------------------------------------
// Kernel 2: distance scan + local top-8. grid (DIST_BLOCKS, B), 256 thr.
// Warp-per-row, 32 rows per warp.
// ---------------------------------------------------------------------------
__global__ void dist_topk_kernel(const float* __restrict__ ctx) {
    int b = blockIdx.y;
    int chunk = blockIdx.x;
    int tid = threadIdx.x;
    int warp = tid >> 5, lane = tid & 31;

    __shared__ float es[DR_];
    __shared__ float s_d2[8][TOPK_];
    __shared__ int   s_ix[8][TOPK_];

    if (tid < DR_) es[tid] = g_e0[b * DR_ + tid];
    __syncthreads();

    const float4* e4 = (const float4*)es;
    float4 ea = e4[lane];
    float4 eb = e4[lane + 32];

    float best[TOPK_];
    int   bidx[TOPK_];
#pragma unroll
    for (int i = 0; i < TOPK_; i++) { best[i] = 3.0e38f; bidx[i] = -1; }

    int row0 = chunk * 256 + warp * 32;
#pragma unroll 2
    for (int r = 0; r < 32; r++) {
        int row = row0 + r;
        const float4* crow = (const float4*)(ctx + ((long)b * M_ + row) * D_);
        float4 ca = crow[lane];
        float4 cb = crow[lane + 32];
        float dx, d2 = 0.f;
        dx = ca.x - ea.x; d2 += dx * dx;
        dx = ca.y - ea.y; d2 += dx * dx;
        dx = ca.z - ea.z; d2 += dx * dx;
        dx = ca.w - ea.w; d2 += dx * dx;
        dx = cb.x - eb.x; d2 += dx * dx;
        dx = cb.y - eb.y; d2 += dx * dx;
        dx = cb.z - eb.z; d2 += dx * dx;
        dx = cb.w - eb.w; d2 += dx * dx;
#pragma unroll
        for (int off = 16; off; off >>= 1)
            d2 += __shfl_down_sync(0xffffffffu, d2, off);
        if (lane == 0 && d2 < best[TOPK_ - 1]) {
            int p = TOPK_ - 1;
            while (p > 0 && best[p - 1] > d2) {
                best[p] = best[p - 1]; bidx[p] = bidx[p - 1]; p--;
            }
            best[p] = d2; bidx[p] = row;
        }
    }

    if (lane == 0) {
#pragma unroll
        for (int i = 0; i < TOPK_; i++) { s_d2[warp][i] = best[i]; s_ix[warp][i] = bidx[i]; }
    }
    __syncthreads();

    if (tid == 0) {
        float fb[TOPK_]; int fi[TOPK_];
#pragma unroll
        for (int i = 0; i < TOPK_; i++) { fb[i] = 3.0e38f; fi[i] = -1; }
        for (int w = 0; w < 8; w++)
            for (int i = 0; i < TOPK_; i++) {
                float d2 = s_d2[w][i];
                if (d2 < fb[TOPK_ - 1]) {
                    int ix = s_ix[w][i];
                    int p = TOPK_ - 1;
                    while (p > 0 && fb[p - 1] > d2) {
                        fb[p] = fb[p - 1]; fi[p] = fi[p - 1]; p--;
                    }
                    fb[p] = d2; fi[p] = ix;
                }
            }
        int off = (b * DIST_BLOCKS + chunk) * TOPK_;
        for (int i = 0; i < TOPK_; i++) { g_cand_d2[off + i] = fb[i]; g_cand_idx[off + i] = fi[i]; }
    }
}

// ---------------------------------------------------------------------------
// Kernel 3: parallel merge -> global per-batch top-8 (u64 keys, argmin x8)
// grid B, 256 threads
// ---------------------------------------------------------------------------
__device__ __forceinline__ unsigned long long u64min(unsigned long long a,
                                                     unsigned long long b) {
    return a < b ? a : b;
}
__global__ void __launch_bounds__(256)
topk_merge_kernel() {
    int b = blockIdx.x;
    int tid = threadIdx.x;
    __shared__ unsigned long long keys[NCAND];
    __shared__ unsigned long long red[256];

    int base = b * NCAND;
    for (int i = tid; i < NCAND; i += 256) {
        float d2 = g_cand_d2[base + i];
        int ix = g_cand_idx[base + i];
        unsigned long long k =
            ((unsigned long long)__float_as_uint(d2) << 32) | (unsigned int)ix;
        if (ix < 0) k = ~0ULL;
        keys[i] = k;
    }
    __syncthreads();

    for (int sel = 0; sel < TOPK_; sel++) {
        unsigned long long m = ~0ULL;
        for (int i = tid; i < NCAND; i += 256) m = u64min(m, keys[i]);
        red[tid] = m;
        __syncthreads();
#pragma unroll
        for (int s = 128; s > 0; s >>= 1) {
            if (tid < s) red[tid] = u64min(red[tid], red[tid + s]);
            __syncthreads();
        }
        unsigned long long w = red[0];
        if (tid == 0)
            g_topk_idx[b * TOPK_ + sel] = (int)(unsigned int)(w & 0xffffffffu);
        for (int i = tid; i < NCAND; i += 256)
            if (keys[i] == w) keys[i] = ~0ULL;
        __syncthreads();
    }
}

// ---------------------------------------------------------------------------
// Kernel 4: fused kv + kappa + vw.  grid (64 bj, 4 slice), 512 thr.
// Each block: gather row, k=labels@Wk, v=reps@Wv (full, cheap);
// then kappa/vw for a 128-wide p/o slice, 2 heads per thread.
// ---------------------------------------------------------------------------
__global__ void __launch_bounds__(512)
kvkv_kernel(const float* __restrict__ ctx,
            const float* __restrict__ Wk,
            const float* __restrict__ Wv,
            const float* __restrict__ Wout) {
    int bj = blockIdx.x;
    int slice = blockIdx.y;
    int b = bj >> 3, j = bj & 7;
    int tid = threadIdx.x;  // 512

    __shared__ float labels[DR_];
    __shared__ float reps[DR_];
    __shared__ float kvec[INNER_];
    __shared__ float vvec[INNER_];

    int row = g_topk_idx[bj];
    const float* crow = ctx + ((long)b * M_ + row) * D_;
    if (tid < 256) reps[tid] = crow[tid];
    else           labels[tid - 256] = crow[tid];
    __syncthreads();

    {
        float ak = 0.f, av = 0.f;
#pragma unroll 8
        for (int r = 0; r < DR_; r++) {
            float l = labels[r], rr = reps[r];
            ak += l * Wk[r * INNER_ + tid];
            av += rr * Wv[r * INNER_ + tid];
        }
        kvec[tid] = ak;
        vvec[tid] = av;
    }
    __syncthreads();

    int hp = tid >> 7;           // 0..3 -> heads hp and hp+4
    int pl = tid & 127;
    int p = slice * 128 + pl;    // p (for kappa) == o (for vw)

    // kappa
    {
        float aK0 = 0.f, aK1 = 0.f;
#pragma unroll 8
        for (int d = 0; d < 64; d++) {
            int i0 = hp * 64 + d;
            int i1 = (hp + 4) * 64 + d;
            aK0 += g_WqT[i0 * 512 + p] * kvec[i0];
            aK1 += g_WqT[i1 * 512 + p] * kvec[i1];
        }
        long kb = ((long)b * 512 + p) * 64 + j * 8;
        g_kappa[kb + hp]     = aK0 * SCALE_;
        g_kappa[kb + hp + 4] = aK1 * SCALE_;
    }

    // vw
    {
        float aV0 = 0.f, aV1 = 0.f;
#pragma unroll 8
        for (int d = 0; d < 64; d++) {
            int i0 = hp * 64 + d;
            int i1 = (hp + 4) * 64 + d;
            aV0 += Wout[i0 * 512 + p] * vvec[i0];
            aV1 += Wout[i1 * 512 + p] * vvec[i1];
        }
        g_vw[((long)b * 64 + j * 8 + hp) * 512 + p]     = aV0;
        g_vw[((long)b * 64 + j * 8 + hp + 4) * 512 + p] = aV1;
    }
}

// ---------------------------------------------------------------------------
// Kernel 5: sim + softmax. grid (16 nchunk, B), 256 thr. M-tile=128 tokens.
// sim[n,c] = x[b,n,:]·kappa[b,:,c]; softmax over j per (token, head).
// ---------------------------------------------------------------------------
__global__ void __launch_bounds__(256)
simA_kernel(const float* __restrict__ x) {
    int nc = blockIdx.x, b = blockIdx.y;
    int n0 = nc * 128;
    int tid = threadIdx.x;
    int ty = tid >> 4, tx = tid & 15;   // ty: 8-row group, tx: 4-col group

    __shared__ float xs[128 * 68];
    __shared__ float ks[64 * 68];

    float acc[8][4];
#pragma unroll
    for (int t = 0; t < 8; t++)
#pragma unroll
        for (int c = 0; c < 4; c++) acc[t][c] = 0.f;

    const float* xb = x + ((long)b * N_ + n0) * QD_;
    const float* kb = g_kappa + (long)b * QD_ * 64;

    for (int pc = 0; pc < 8; pc++) {
        int p0 = pc * 64;
#pragma unroll
        for (int l = 0; l < 8; l++) {
            int f = tid + l * 256;
            int row = f >> 4, c4 = (f & 15) * 4;
            *(float4*)&xs[row * 68 + c4] =
                *(const float4*)(xb + (long)row * QD_ + p0 + c4);
        }
#pragma unroll
        for (int l = 0; l < 4; l++) {
            int f = tid + l * 256;
            int row = f >> 4, c4 = (f & 15) * 4;
            *(float4*)&ks[row * 68 + c4] =
                *(const float4*)(kb + (long)(p0 + row) * 64 + c4);
        }
        __syncthreads();
#pragma unroll
        for (int kk = 0; kk < 64; kk += 4) {
            float4 av[8], bv[4];
#pragma unroll
            for (int t = 0; t < 8; t++)
                av[t] = *(const float4*)&xs[(ty * 8 + t) * 68 + kk];
#pragma unroll
            for (int cc = 0; cc < 4; cc++)
                bv[cc] = *(const float4*)&ks[(kk + cc) * 68 + tx * 4];
#pragma unroll
            for (int t = 0; t < 8; t++) {
                acc[t][0] += av[t].x * bv[0].x; acc[t][1] += av[t].x * bv[0].y;
                acc[t][2] += av[t].x * bv[0].z; acc[t][3] += av[t].x * bv[0].w;
                acc[t][0] += av[t].y * bv[1].x; acc[t][1] += av[t].y * bv[1].y;
                acc[t][2] += av[t].y * bv[1].z; acc[t][3] += av[t].y * bv[1].w;
                acc[t][0] += av[t].z * bv[2].x; acc[t][1] += av[t].z * bv[2].y;
                acc[t][2] += av[t].z * bv[2].z; acc[t][3] += av[t].z * bv[2].w;
                acc[t][0] += av[t].w * bv[3].x; acc[t][1] += av[t].w * bv[3].y;
                acc[t][2] += av[t].w * bv[3].z; acc[t][3] += av[t].w * bv[3].w;
            }
        }
        __syncthreads();
    }

    // dump sim into xs
#pragma unroll
    for (int t = 0; t < 8; t++) {
        float4 v = make_float4(acc[t][0], acc[t][1], acc[t][2], acc[t][3]);
        *(float4*)&xs[(ty * 8 + t) * 68 + tx * 4] = v;
    }
    __syncthreads();

    // softmax: 128 tokens x 8 heads = 1024 tasks, 4 per thread
#pragma unroll
    for (int s = 0; s < 4; s++) {
        int task = s * 256 + tid;
        int t = task >> 3, h = task & 7;
        float v[8];
#pragma unroll
        for (int jj = 0; jj < 8; jj++) v[jj] = xs[t * 68 + jj * 8 + h];
        float m = v[0];
#pragma unroll
        for (int jj = 1; jj < 8; jj++) m = fmaxf(m, v[jj]);
        float e[8], sum = 0.f;
#pragma unroll
        for (int jj = 0; jj < 8; jj++) { e[jj] = __expf(v[jj] - m); sum += e[jj]; }
        float inv = 1.f / sum;
        float* arow = g_a + ((long)b * N_ + n0 + t) * 64;
#pragma unroll
        for (int jj = 0; jj < 8; jj++) arow[jj * 8 + h] = e[jj] * inv;
    }
}

// ---------------------------------------------------------------------------
// Kernel 6: out[n,o] = sum_c a[n,c]*vw[c,o] + bout[o]
// grid (8 oc, 32 nc, B), 256 thr
// ---------------------------------------------------------------------------
__global__ void __launch_bounds__(256)
outB_kernel(float* __restrict__ out, const float* __restrict__ bout) {
    int oc = blockIdx.x, nc = blockIdx.y, b = blockIdx.z;
    int o0 = oc * 64, n0 = nc * 64;
    int tid = threadIdx.x;
    int ty = tid >> 4, tx = tid & 15;

    __shared__ float as_[64 * 68];
    __shared__ float vws[64 * 68];

#pragma unroll
    for (int l = 0; l < 4; l++) {
        int f = tid + l * 256;
        int row = f >> 4, c4 = (f & 15) * 4;
        *(float4*)&as_[row * 68 + c4] =
            *(const float4*)(g_a + ((long)b * N_ + n0 + row) * 64 + c4);
        *(float4*)&vws[row * 68 + c4] =
            *(const float4*)(g_vw + ((long)b * 64 + row) * 512 + o0 + c4);
    }
    __syncthreads();

    float acc[4][4];
#pragma unroll
    for (int t = 0; t < 4; t++)
#pragma unroll
        for (int o = 0; o < 4; o++) acc[t][o] = 0.f;

#pragma unroll
    for (int c = 0; c < 64; c += 4) {
        float4 av[4], bv[4];
#pragma unroll
        for (int t = 0; t < 4; t++) av[t] = *(const float4*)&as_[(ty * 4 + t) * 68 + c];
#pragma unroll
        for (int cc = 0; cc < 4; cc++) bv[cc] = *(const float4*)&vws[(c + cc) * 68 + tx * 4];
#pragma unroll
        for (int t = 0; t < 4; t++) {
            acc[t][0] += av[t].x * bv[0].x; acc[t][1] += av[t].x * bv[0].y;
            acc[t][2] += av[t].x * bv[0].z; acc[t][3] += av[t].x * bv[0].w;
            acc[t][0] += av[t].y * bv[1].x; acc[t][1] += av[t].y * bv[1].y;
            acc[t][2] += av[t].y * bv[1].z; acc[t][3] += av[t].y * bv[1].w;
            acc[t][0] += av[t].z * bv[2].x; acc[t][1] += av[t].z * bv[2].y;
            acc[t][2] += av[t].z * bv[2].z; acc[t][3] += av[t].z * bv[2].w;
            acc[t][0] += av[t].w * bv[3].x; acc[t][1] += av[t].w * bv[3].y;
            acc[t][2] += av[t].w * bv[3].z; acc[t][3] += av[t].w * bv[3].w;
        }
    }

    float4 bias = *(const float4*)(bout + o0 + tx * 4);
#pragma unroll
    for (int t = 0; t < 4; t++) {
        float4 r = make_float4(acc[t][0] + bias.x, acc[t][1] + bias.y,
                               acc[t][2] + bias.z, acc[t][3] + bias.w);
        *(float4*)(out + ((long)b * N_ + n0 + ty * 4 + t) * 512 + o0 + tx * 4) = r;
    }
}

// ---------------------------------------------------------------------------
// Launch
// ---------------------------------------------------------------------------
extern "C" void kernel_launch(void* const* d_in, const int* in_sizes, int n_in,
                              void* d_out, int out_size) {
    const float* x    = (const float*)d_in[0];
    const float* ctx  = (const float*)d_in[1];
    const float* Wq   = (const float*)d_in[2];
    const float* Wk   = (const float*)d_in[3];
    const float* Wv   = (const float*)d_in[4];
    const float* We   = (const float*)d_in[5];
    const float* Wout = (const float*)d_in[6];
    const float* bout = (const float*)d_in[7];
    float* out = (float*)d_out;

    transpose512<<<dim3(16, 16), 256>>>(Wq);
    e0_kernel<<<B_, 512>>>(x, Wq, We);
    dist_topk_kernel<<<dim3(DIST_BLOCKS, B_), 256>>>(ctx);
    topk_merge_kernel<<<B_, 256>>>();
    kvkv_kernel<<<dim3(64, 4), 512>>>(ctx, Wk, Wv, Wout);
    simA_kernel<<<dim3(16, B_), 256>>>(x);
    outB_kernel<<<dim3(8, 32, B_), 256>>>(out, bout);
}